// round 9
// baseline (speedup 1.0000x reference)
#include <cuda_runtime.h>
#include <cuda_bf16.h>
#include <cstdint>

// PoseDisentangler: bone_len + bone_dir from H36M skeleton.
// pose_3d: (B=128, N=4096, J=17, 3) fp32, row of 51 floats per (b,n).
// out: [bone_len (B*N*16)] ++ [bone_dir (B*N*48)]
//
// R8: R5 structure (smem transpose for coalesced stores) +
//  - single rsqrtf per bone (len = ss*inv) -> kills IEEE-sqrt fixup chain
//  - 64 rows / 256 threads -> 7 CTAs/SM, 87.5% occupancy

#define ROWS 64                 // rows per block
#define THREADS 256
#define ROW_FLOATS 51           // 17 joints * 3
#define NB 16                   // bones
#define IN_F4 (ROWS * ROW_FLOATS / 4)   // 816 float4 per block
#define DIR_STRIDE 52           // padded dir row stride (floats)

// PARENT[j] packed 4 bits per bone: {0,1,2,0,4,5,0,7,8,9,8,11,12,8,14,15}
#define PARENT_PACK 0xFE8CB89870540210ULL
__device__ __forceinline__ int parent_of(int j) {
    return (int)((PARENT_PACK >> (j * 4)) & 15ULL);
}

__global__ __launch_bounds__(THREADS, 7)
void pose_bones_kernel(const float* __restrict__ in,
                       float* __restrict__ len_out,
                       float* __restrict__ dir_out)
{
    __shared__ float s_in[ROWS * ROW_FLOATS];      // 13056 B
    __shared__ float s_len[ROWS * NB];             //  4096 B
    __shared__ float s_dir[ROWS * DIR_STRIDE];     // 13312 B

    const int tid = threadIdx.x;

    // Stage input: 816 float4, coalesced (block base 13056B*blockIdx, 128B-aligned).
    {
        const float4* __restrict__ gin =
            reinterpret_cast<const float4*>(in) + (size_t)blockIdx.x * IN_F4;
        float4* s4 = reinterpret_cast<float4*>(s_in);
        #pragma unroll
        for (int k = 0; k < 4; ++k) {
            int idx = tid + k * THREADS;
            if (idx < IN_F4)                       // 816 (3 full iters + 48)
                s4[idx] = gin[idx];
        }
    }
    __syncthreads();

    // Compute: thread (row = tid>>2, q = tid&3) does bones 4q..4q+3, once each.
    {
        const int row = tid >> 2;
        const int q   = tid & 3;
        const float* __restrict__ p = s_in + row * ROW_FLOATS;

        float l[4];
        float d[12];
        #pragma unroll
        for (int jj = 0; jj < 4; ++jj) {
            const int j  = q * 4 + jj;
            const int ch = (j + 1) * 3;
            const int pa = parent_of(j) * 3;
            float vx = p[ch + 0] - p[pa + 0];
            float vy = p[ch + 1] - p[pa + 1];
            float vz = p[ch + 2] - p[pa + 2];
            float ss  = fmaxf(vx * vx + vy * vy + vz * vz, 1e-30f);
            float inv = rsqrtf(ss);                // single MUFU, ~2ulp
            l[jj]         = ss * inv;              // == sqrt(ss)
            d[jj * 3 + 0] = vx * inv;
            d[jj * 3 + 1] = vy * inv;
            d[jj * 3 + 2] = vz * inv;
        }

        // len: 4 floats at s_len[row*16 + 4q] (16B aligned)
        *reinterpret_cast<float4*>(s_len + row * NB + q * 4) =
            make_float4(l[0], l[1], l[2], l[3]);
        // dir: 12 floats at s_dir[row*52 + 12q] (16B aligned)
        float4* sd = reinterpret_cast<float4*>(s_dir + row * DIR_STRIDE + q * 12);
        sd[0] = make_float4(d[0], d[1], d[2],  d[3]);
        sd[1] = make_float4(d[4], d[5], d[6],  d[7]);
        sd[2] = make_float4(d[8], d[9], d[10], d[11]);
    }
    __syncthreads();

    // Coalesced readback -> global.
    // len: block region = 64*16 floats = 256 float4, contiguous. 1 per thread.
    {
        const float4* sl4 = reinterpret_cast<const float4*>(s_len);
        float4* __restrict__ lo =
            reinterpret_cast<float4*>(len_out) + (size_t)blockIdx.x * (ROWS * NB / 4);
        lo[tid] = sl4[tid];
    }
    // dir: block region = 64*48 floats = 768 float4, contiguous. 3 per thread.
    // smem f4 index for global f4 g: row = g/12 -> g + row (row stride 13 f4).
    {
        const float4* sd4 = reinterpret_cast<const float4*>(s_dir);
        float4* __restrict__ dd =
            reinterpret_cast<float4*>(dir_out) + (size_t)blockIdx.x * (ROWS * NB * 3 / 4);
        #pragma unroll
        for (int k = 0; k < 3; ++k) {
            int g = tid + k * THREADS;             // 0..767
            int r = g / 12;
            dd[g] = sd4[g + r];
        }
    }
}

extern "C" void kernel_launch(void* const* d_in, const int* in_sizes, int n_in,
                              void* d_out, int out_size)
{
    const float* in = (const float*)d_in[0];
    const int rows = in_sizes[0] / ROW_FLOATS;         // B*N = 524288

    float* len_out = (float*)d_out;
    float* dir_out = len_out + (size_t)rows * NB;

    const int blocks = rows / ROWS;                    // exact: 8192
    pose_bones_kernel<<<blocks, THREADS>>>(in, len_out, dir_out);
}

// round 11
// speedup vs baseline: 1.0374x; 1.0374x over previous
#include <cuda_runtime.h>
#include <cuda_bf16.h>
#include <cstdint>

// PoseDisentangler: bone_len + bone_dir from H36M skeleton.
// pose_3d: (B=128, N=4096, J=17, 3) fp32, row of 51 floats per (b,n).
// out: [bone_len (B*N*16)] ++ [bone_dir (B*N*48)]
//
// R10: R5 winning shape (32 rows / 128 threads, smem transpose for fully
// coalesced stores) + rsqrt-only math (no IEEE sqrt chain) + 15 CTAs/SM
// (14.7KB smem/CTA; 15*128 = 1920 thr/SM = 93.8% occ).

#define ROWS 32                 // rows per block
#define THREADS 128
#define ROW_FLOATS 51           // 17 joints * 3
#define NB 16                   // bones
#define IN_F4 (ROWS * ROW_FLOATS / 4)   // 408 float4 per block
#define DIR_STRIDE 52           // padded dir row stride (floats)

// PARENT[j] packed 4 bits per bone: {0,1,2,0,4,5,0,7,8,9,8,11,12,8,14,15}
#define PARENT_PACK 0xFE8CB89870540210ULL
__device__ __forceinline__ int parent_of(int j) {
    return (int)((PARENT_PACK >> (j * 4)) & 15ULL);
}

__global__ __launch_bounds__(THREADS, 15)
void pose_bones_kernel(const float* __restrict__ in,
                       float* __restrict__ len_out,
                       float* __restrict__ dir_out)
{
    __shared__ float s_in[ROWS * ROW_FLOATS];      // 6528 B
    __shared__ float s_len[ROWS * NB];             // 2048 B
    __shared__ float s_dir[ROWS * DIR_STRIDE];     // 6656 B

    const int tid = threadIdx.x;

    // Stage input: 408 float4, coalesced (block base 6528B*blockIdx, 128B-aligned).
    {
        const float4* __restrict__ gin =
            reinterpret_cast<const float4*>(in) + (size_t)blockIdx.x * IN_F4;
        float4* s4 = reinterpret_cast<float4*>(s_in);
        #pragma unroll
        for (int k = 0; k < 4; ++k) {
            int idx = tid + k * THREADS;
            if (idx < IN_F4)                       // 408
                s4[idx] = gin[idx];
        }
    }
    __syncthreads();

    // Compute: thread (row = tid>>2, q = tid&3) does bones 4q..4q+3, once each.
    {
        const int row = tid >> 2;
        const int q   = tid & 3;
        const float* __restrict__ p = s_in + row * ROW_FLOATS;

        float l[4];
        float d[12];
        #pragma unroll
        for (int jj = 0; jj < 4; ++jj) {
            const int j  = q * 4 + jj;
            const int ch = (j + 1) * 3;
            const int pa = parent_of(j) * 3;
            float vx = p[ch + 0] - p[pa + 0];
            float vy = p[ch + 1] - p[pa + 1];
            float vz = p[ch + 2] - p[pa + 2];
            float ss  = fmaxf(vx * vx + vy * vy + vz * vz, 1e-30f);
            float inv = rsqrtf(ss);                // single MUFU, ~2ulp
            l[jj]         = ss * inv;              // == sqrt(ss)
            d[jj * 3 + 0] = vx * inv;
            d[jj * 3 + 1] = vy * inv;
            d[jj * 3 + 2] = vz * inv;
        }

        // len: 4 floats at s_len[row*16 + 4q] (16B aligned)
        *reinterpret_cast<float4*>(s_len + row * NB + q * 4) =
            make_float4(l[0], l[1], l[2], l[3]);
        // dir: 12 floats at s_dir[row*52 + 12q] (16B aligned)
        float4* sd = reinterpret_cast<float4*>(s_dir + row * DIR_STRIDE + q * 12);
        sd[0] = make_float4(d[0], d[1], d[2],  d[3]);
        sd[1] = make_float4(d[4], d[5], d[6],  d[7]);
        sd[2] = make_float4(d[8], d[9], d[10], d[11]);
    }
    __syncthreads();

    // Coalesced readback -> global.
    // len: block region = 32*16 floats = 128 float4, contiguous. 1 per thread.
    {
        const float4* sl4 = reinterpret_cast<const float4*>(s_len);
        float4* __restrict__ lo =
            reinterpret_cast<float4*>(len_out) + (size_t)blockIdx.x * (ROWS * NB / 4);
        lo[tid] = sl4[tid];
    }
    // dir: block region = 32*48 floats = 384 float4, contiguous. 3 per thread.
    // smem f4 index for global f4 g: row = g/12 -> g + row (row stride 13 f4).
    {
        const float4* sd4 = reinterpret_cast<const float4*>(s_dir);
        float4* __restrict__ dd =
            reinterpret_cast<float4*>(dir_out) + (size_t)blockIdx.x * (ROWS * NB * 3 / 4);
        #pragma unroll
        for (int k = 0; k < 3; ++k) {
            int g = tid + k * THREADS;             // 0..383
            int r = g / 12;
            dd[g] = sd4[g + r];
        }
    }
}

extern "C" void kernel_launch(void* const* d_in, const int* in_sizes, int n_in,
                              void* d_out, int out_size)
{
    const float* in = (const float*)d_in[0];
    const int rows = in_sizes[0] / ROW_FLOATS;         // B*N = 524288

    float* len_out = (float*)d_out;
    float* dir_out = len_out + (size_t)rows * NB;

    const int blocks = rows / ROWS;                    // exact: 16384
    pose_bones_kernel<<<blocks, THREADS>>>(in, len_out, dir_out);
}